// round 6
// baseline (speedup 1.0000x reference)
#include <cuda_runtime.h>
#include <cstdint>

#define N_NODES 100000
#define E_EDGES 3200000
#define IN_DIM  256
#define OUT_DIM 64
#define LN_EPS  1e-5f
#define NEG_SLOPE 0.01f

// Scratch (no allocations allowed -> __device__ globals). 16B-aligned for v4 ops.
__device__ __align__(16) float g_deg[N_NODES];
__device__ __align__(16) float g_hs [N_NODES * OUT_DIM];  // (x@W)*rsqrt(deg[row])
__device__ __align__(16) float g_acc[N_NODES * OUT_DIM];  // accumulator, init = g_hs

// ---------------------------------------------------------------------------
// 1) deg init (self-loop weight 1)
// ---------------------------------------------------------------------------
__global__ void k_init_deg() {
    int i = blockIdx.x * blockDim.x + threadIdx.x;
    if (i < N_NODES) g_deg[i] = 1.0f;
}

// ---------------------------------------------------------------------------
// 2) deg[dst] += ew   (spread atomics, L2-resident 400KB)
// ---------------------------------------------------------------------------
__global__ void k_deg_scatter(const int* __restrict__ ei, const float* __restrict__ ew) {
    int e = blockIdx.x * blockDim.x + threadIdx.x;
    if (e < E_EDGES) atomicAdd(&g_deg[ei[E_EDGES + e]], ew[e]);
}

// ---------------------------------------------------------------------------
// 3) GEMM (tf32 tensor cores, 3-term split for fp32-grade accuracy):
//    hs = (x @ W) * rsqrt(deg), acc = hs.
//    mma A = W^T tile [outcol][k], mma B = x tile [node][k].
//    Block = 128 nodes x 64 outcols, k chunked 2x128. Padded stride 132.
//    R5 BUG FIX: W staging loop now i<8 (2048 float4), was i<4 (half tile stale).
// ---------------------------------------------------------------------------
#define GEMM_ROWS 128
#define KC  128          // k-chunk
#define SP  132          // padded smem stride (floats)
#define OSP 68           // padded output-transpose stride (floats)

__device__ __forceinline__ uint32_t f2tf32(float f) {
    uint32_t r;
    asm("cvt.rna.tf32.f32 %0, %1;" : "=r"(r) : "f"(f));
    return r;
}

__device__ __forceinline__ void mma_tf32(float c[4], const uint32_t a[4],
                                         uint32_t b0, uint32_t b1) {
    asm volatile(
        "mma.sync.aligned.m16n8k8.row.col.f32.tf32.tf32.f32 "
        "{%0,%1,%2,%3}, {%4,%5,%6,%7}, {%8,%9}, {%0,%1,%2,%3};"
        : "+f"(c[0]), "+f"(c[1]), "+f"(c[2]), "+f"(c[3])
        : "r"(a[0]), "r"(a[1]), "r"(a[2]), "r"(a[3]), "r"(b0), "r"(b1));
}

__global__ void __launch_bounds__(256, 1) k_gemm(const float* __restrict__ x,
                                                 const float* __restrict__ W) {
    extern __shared__ float sm[];
    float* xs_hi = sm;                        // [128][SP]
    float* xs_lo = xs_hi + GEMM_ROWS * SP;    // [128][SP]
    float* wt_hi = xs_lo + GEMM_ROWS * SP;    // [64][SP]  (transposed W: [outcol][k])
    float* wt_lo = wt_hi + OUT_DIM * SP;      // [64][SP]

    const int tid   = threadIdx.x;
    const int node0 = blockIdx.x * GEMM_ROWS;
    const int wid   = tid >> 5;
    const int lane  = tid & 31;
    const int g     = lane >> 2;      // groupID
    const int t     = lane & 3;       // thread-in-group
    const int mi    = wid & 3;        // m-tile (16 outcols)
    const int nh    = wid >> 2;       // node half (64 nodes)
    const int m0    = mi * 16;
    const int nb    = nh * 64;

    float c[8][4];
    #pragma unroll
    for (int j = 0; j < 8; j++)
        #pragma unroll
        for (int q = 0; q < 4; q++) c[j][q] = 0.f;

    for (int ch = 0; ch < 2; ch++) {
        const int k0c = ch * KC;

        // --- load W chunk transposed + split: wt[outcol][kk] ---
        // chunk = 128 k-rows x 64 cols = 2048 float4 -> 8 iters of 256 threads
        for (int i = 0; i < 8; i++) {
            int idx4 = tid + 256 * i;                // float4 over W chunk
            int n4   = idx4 & 15;                    // 16 float4 per k-row
            int kk   = idx4 >> 4;                    // 0..127
            float4 v = ((const float4*)W)[(size_t)(k0c + kk) * 16 + n4];
            float vs[4] = {v.x, v.y, v.z, v.w};
            #pragma unroll
            for (int q = 0; q < 4; q++) {
                float hi = __uint_as_float(f2tf32(vs[q]));
                wt_hi[(n4 * 4 + q) * SP + kk] = hi;
                wt_lo[(n4 * 4 + q) * SP + kk] = vs[q] - hi;
            }
        }
        // --- load x chunk + split: xs[node][kk] ---
        for (int i = 0; i < 16; i++) {
            int idx4 = tid + 256 * i;                // 4096 float4
            int k4   = idx4 & 31;                    // 32 float4 per row-chunk
            int r    = idx4 >> 5;                    // 0..127
            int gr   = node0 + r;
            float4 v = (gr < N_NODES)
                     ? ((const float4*)x)[(size_t)gr * 64 + (k0c >> 2) + k4]
                     : make_float4(0.f, 0.f, 0.f, 0.f);
            float vs[4] = {v.x, v.y, v.z, v.w};
            #pragma unroll
            for (int q = 0; q < 4; q++) {
                float hi = __uint_as_float(f2tf32(vs[q]));
                xs_hi[r * SP + k4 * 4 + q] = hi;
                xs_lo[r * SP + k4 * 4 + q] = vs[q] - hi;
            }
        }
        __syncthreads();

        #pragma unroll 4
        for (int ks = 0; ks < KC / 8; ks++) {
            const int k0 = ks * 8;
            uint32_t ah[4], al[4];
            // A = W^T fragment: rows m0+g(+8), cols k0+t(+4)
            ah[0] = __float_as_uint(wt_hi[(m0 + g)     * SP + k0 + t]);
            ah[1] = __float_as_uint(wt_hi[(m0 + g + 8) * SP + k0 + t]);
            ah[2] = __float_as_uint(wt_hi[(m0 + g)     * SP + k0 + t + 4]);
            ah[3] = __float_as_uint(wt_hi[(m0 + g + 8) * SP + k0 + t + 4]);
            al[0] = __float_as_uint(wt_lo[(m0 + g)     * SP + k0 + t]);
            al[1] = __float_as_uint(wt_lo[(m0 + g + 8) * SP + k0 + t]);
            al[2] = __float_as_uint(wt_lo[(m0 + g)     * SP + k0 + t + 4]);
            al[3] = __float_as_uint(wt_lo[(m0 + g + 8) * SP + k0 + t + 4]);

            #pragma unroll
            for (int j = 0; j < 8; j++) {
                const int n0 = nb + j * 8;
                // B = x fragment: col(n)=g, row(k)=t(+4)
                uint32_t bh0 = __float_as_uint(xs_hi[(n0 + g) * SP + k0 + t]);
                uint32_t bh1 = __float_as_uint(xs_hi[(n0 + g) * SP + k0 + t + 4]);
                uint32_t bl0 = __float_as_uint(xs_lo[(n0 + g) * SP + k0 + t]);
                uint32_t bl1 = __float_as_uint(xs_lo[(n0 + g) * SP + k0 + t + 4]);
                mma_tf32(c[j], ah, bh0, bh1);
                mma_tf32(c[j], al, bh0, bh1);
                mma_tf32(c[j], ah, bl0, bl1);
            }
        }
        __syncthreads();
    }

    // --- transpose result through smem -> coalesced float4 global stores ---
    float* smo = sm;  // [128][OSP], 34.8KB, reuses xs area
    #pragma unroll
    for (int j = 0; j < 8; j++) {
        const int nloc = nb + j * 8 + 2 * t;
        smo[(nloc)     * OSP + m0 + g]     = c[j][0];
        smo[(nloc + 1) * OSP + m0 + g]     = c[j][1];
        smo[(nloc)     * OSP + m0 + g + 8] = c[j][2];
        smo[(nloc + 1) * OSP + m0 + g + 8] = c[j][3];
    }
    __syncthreads();

    for (int i = 0; i < 8; i++) {
        int idx4 = tid + 256 * i;          // 2048 float4 = 128 rows x 16
        int r    = idx4 >> 4;
        int c4   = idx4 & 15;
        int gn   = node0 + r;
        if (gn < N_NODES) {
            float rs = rsqrtf(g_deg[gn]);
            float4 v = *(float4*)&smo[r * OSP + c4 * 4];
            v.x *= rs; v.y *= rs; v.z *= rs; v.w *= rs;
            ((float4*)g_hs)[(size_t)gn * 16 + c4]  = v;
            ((float4*)g_acc)[(size_t)gn * 16 + c4] = v;   // self-loop term
        }
    }
}

// ---------------------------------------------------------------------------
// 4) edge scatter: acc[dst] += hs[src] * ew   (R4 winner — unchanged)
//    16 threads/edge, coalesced; 1 ld.v4 + 1 red.global.add.v4.f32 per lane.
// ---------------------------------------------------------------------------
__device__ __forceinline__ void red_v4(float* addr, float a, float b, float c, float d) {
    asm volatile("red.global.add.v4.f32 [%0], {%1, %2, %3, %4};"
                 :: "l"(addr), "f"(a), "f"(b), "f"(c), "f"(d) : "memory");
}

__global__ void __launch_bounds__(256) k_scatter(const int* __restrict__ ei,
                                                 const float* __restrict__ ew) {
    int t = blockIdx.x * blockDim.x + threadIdx.x;
    int e = t >> 4;
    if (e >= E_EDGES) return;
    int part = t & 15;

    const int   src = ei[e];
    const int   dst = ei[E_EDGES + e];
    const float w   = ew[e];

    float4 m = *(const float4*)&g_hs[src * OUT_DIM + (part << 2)];
    red_v4(&g_acc[dst * OUT_DIM + (part << 2)], m.x * w, m.y * w, m.z * w, m.w * w);
}

// ---------------------------------------------------------------------------
// 5) finalize: y = acc*dinv + b -> leaky_relu -> LayerNorm -> out
// ---------------------------------------------------------------------------
__global__ void k_finalize(const float* __restrict__ b, const float* __restrict__ gamma,
                           const float* __restrict__ beta, float* __restrict__ out) {
    int gw   = (blockIdx.x * blockDim.x + threadIdx.x) >> 5;
    int lane = threadIdx.x & 31;
    if (gw >= N_NODES) return;

    float dinv = rsqrtf(g_deg[gw]);
    int c0 = lane << 1;

    float2 a = *(const float2*)&g_acc[gw * OUT_DIM + c0];
    float y0 = a.x * dinv + b[c0];
    float y1 = a.y * dinv + b[c0 + 1];
    y0 = (y0 >= 0.f) ? y0 : NEG_SLOPE * y0;
    y1 = (y1 >= 0.f) ? y1 : NEG_SLOPE * y1;

    float s  = y0 + y1;
    float sq = y0 * y0 + y1 * y1;
    #pragma unroll
    for (int off = 16; off > 0; off >>= 1) {
        s  += __shfl_xor_sync(0xFFFFFFFFu, s,  off);
        sq += __shfl_xor_sync(0xFFFFFFFFu, sq, off);
    }
    float mu  = s * (1.f / 64.f);
    float var = sq * (1.f / 64.f) - mu * mu;
    float inv = rsqrtf(var + LN_EPS);

    float o0 = (y0 - mu) * inv * gamma[c0]     + beta[c0];
    float o1 = (y1 - mu) * inv * gamma[c0 + 1] + beta[c0 + 1];
    float2 r; r.x = o0; r.y = o1;
    *(float2*)&out[gw * OUT_DIM + c0] = r;
}

// ---------------------------------------------------------------------------
extern "C" void kernel_launch(void* const* d_in, const int* in_sizes, int n_in,
                              void* d_out, int out_size) {
    const float* x     = (const float*)d_in[0];
    const int*   ei    = (const int*)  d_in[1];
    const float* ew    = (const float*)d_in[2];
    const float* W     = (const float*)d_in[3];
    const float* b     = (const float*)d_in[4];
    const float* gamma = (const float*)d_in[5];
    const float* beta  = (const float*)d_in[6];
    float* out = (float*)d_out;

    const int gemm_smem = (2 * GEMM_ROWS * SP + 2 * OUT_DIM * SP) * (int)sizeof(float);
    cudaFuncSetAttribute(k_gemm, cudaFuncAttributeMaxDynamicSharedMemorySize, gemm_smem);

    k_init_deg   <<<(N_NODES + 255) / 256, 256>>>();
    k_deg_scatter<<<(E_EDGES + 255) / 256, 256>>>(ei, ew);
    k_gemm       <<<(N_NODES + GEMM_ROWS - 1) / GEMM_ROWS, 256, gemm_smem>>>(x, W);
    k_scatter    <<<((long long)E_EDGES * 16 + 255) / 256, 256>>>(ei, ew);
    k_finalize   <<<(N_NODES * 32 + 255) / 256, 256>>>(b, gamma, beta, out);
}

// round 10
// speedup vs baseline: 1.1181x; 1.1181x over previous
#include <cuda_runtime.h>
#include <cstdint>

#define N_NODES 100000
#define E_EDGES 3200000
#define IN_DIM  256
#define OUT_DIM 64
#define LN_EPS  1e-5f
#define NEG_SLOPE 0.01f

// Scratch (no allocations allowed -> __device__ globals). 16B-aligned for v4 ops.
__device__ __align__(16) float g_deg[N_NODES];
__device__ __align__(16) float g_hs [N_NODES * OUT_DIM];  // (x@W)*rsqrt(deg[row])
__device__ __align__(16) float g_acc[N_NODES * OUT_DIM];  // accumulator, init = g_hs

// ---------------------------------------------------------------------------
// 1) deg init (self-loop weight 1)
// ---------------------------------------------------------------------------
__global__ void k_init_deg() {
    int i = blockIdx.x * blockDim.x + threadIdx.x;
    if (i < N_NODES) g_deg[i] = 1.0f;
}

// ---------------------------------------------------------------------------
// 2) deg[dst] += ew   (spread atomics, L2-resident 400KB)
// ---------------------------------------------------------------------------
__global__ void k_deg_scatter(const int* __restrict__ ei, const float* __restrict__ ew) {
    int e = blockIdx.x * blockDim.x + threadIdx.x;
    if (e < E_EDGES) atomicAdd(&g_deg[ei[E_EDGES + e]], ew[e]);
}

// ---------------------------------------------------------------------------
// 3) GEMM (tf32 tensor cores, 3-term split, fp32-grade accuracy):
//    hs = (x @ W) * rsqrt(deg), acc = hs.
//    R6 -> R7: smem holds fp32 ONLY (no hi/lo planes); hi/lo derived in
//    registers at fragment load. 202KB -> 101KB smem => 2 blocks/SM (16 warps),
//    mainloop LDS halved (20/ks vs 40/ks), staging stores halved, no cvt there.
// ---------------------------------------------------------------------------
#define GEMM_ROWS 128
#define KC  128          // k-chunk
#define SP  132          // padded smem stride (floats) -> frag bank = 4g+t (no conflict)
#define OSP 68           // padded output-transpose stride (floats)

__device__ __forceinline__ uint32_t f2tf32(float f) {
    uint32_t r;
    asm("cvt.rna.tf32.f32 %0, %1;" : "=r"(r) : "f"(f));
    return r;
}

__device__ __forceinline__ void mma_tf32(float c[4], const uint32_t a[4],
                                         uint32_t b0, uint32_t b1) {
    asm volatile(
        "mma.sync.aligned.m16n8k8.row.col.f32.tf32.tf32.f32 "
        "{%0,%1,%2,%3}, {%4,%5,%6,%7}, {%8,%9}, {%0,%1,%2,%3};"
        : "+f"(c[0]), "+f"(c[1]), "+f"(c[2]), "+f"(c[3])
        : "r"(a[0]), "r"(a[1]), "r"(a[2]), "r"(a[3]), "r"(b0), "r"(b1));
}

__global__ void __launch_bounds__(256, 2) k_gemm(const float* __restrict__ x,
                                                 const float* __restrict__ W) {
    extern __shared__ float sm[];
    float* xs = sm;                       // [128][SP]  fp32 x tile [node][k]
    float* wt = xs + GEMM_ROWS * SP;      // [64][SP]   fp32 W^T tile [outcol][k]

    const int tid   = threadIdx.x;
    const int node0 = blockIdx.x * GEMM_ROWS;
    const int wid   = tid >> 5;
    const int lane  = tid & 31;
    const int g     = lane >> 2;      // groupID
    const int t     = lane & 3;       // thread-in-group
    const int mi    = wid & 3;        // m-tile (16 outcols)
    const int nh    = wid >> 2;       // node half (64 nodes)
    const int m0    = mi * 16;
    const int nb    = nh * 64;

    float c[8][4];
    #pragma unroll
    for (int j = 0; j < 8; j++)
        #pragma unroll
        for (int q = 0; q < 4; q++) c[j][q] = 0.f;

    for (int ch = 0; ch < 2; ch++) {
        const int k0c = ch * KC;

        // --- stage W chunk transposed (fp32): wt[outcol][kk] ---
        // chunk = 128 k-rows x 64 cols = 2048 float4 -> 8 iters x 256 threads
        for (int i = 0; i < 8; i++) {
            int idx4 = tid + 256 * i;
            int n4   = idx4 & 15;                    // 16 float4 per k-row
            int kk   = idx4 >> 4;                    // 0..127
            float4 v = ((const float4*)W)[(size_t)(k0c + kk) * 16 + n4];
            wt[(n4 * 4 + 0) * SP + kk] = v.x;
            wt[(n4 * 4 + 1) * SP + kk] = v.y;
            wt[(n4 * 4 + 2) * SP + kk] = v.z;
            wt[(n4 * 4 + 3) * SP + kk] = v.w;
        }
        // --- stage x chunk (fp32, vector stores): xs[node][kk] ---
        for (int i = 0; i < 16; i++) {
            int idx4 = tid + 256 * i;                // 4096 float4
            int k4   = idx4 & 31;                    // 32 float4 per row-chunk
            int r    = idx4 >> 5;                    // 0..127
            int gr   = node0 + r;
            float4 v = (gr < N_NODES)
                     ? ((const float4*)x)[(size_t)gr * 64 + (k0c >> 2) + k4]
                     : make_float4(0.f, 0.f, 0.f, 0.f);
            *(float4*)&xs[r * SP + k4 * 4] = v;
        }
        __syncthreads();

        #pragma unroll 4
        for (int ks = 0; ks < KC / 8; ks++) {
            const int k0 = ks * 8;
            // A = W^T fragment (fp32 from smem), hi/lo derived in regs
            float af[4];
            af[0] = wt[(m0 + g)     * SP + k0 + t];
            af[1] = wt[(m0 + g + 8) * SP + k0 + t];
            af[2] = wt[(m0 + g)     * SP + k0 + t + 4];
            af[3] = wt[(m0 + g + 8) * SP + k0 + t + 4];
            uint32_t ah[4], al[4];
            #pragma unroll
            for (int q = 0; q < 4; q++) {
                ah[q] = f2tf32(af[q]);
                al[q] = __float_as_uint(af[q] - __uint_as_float(ah[q]));
            }

            #pragma unroll
            for (int j = 0; j < 8; j++) {
                const int n0 = nb + j * 8;
                float b0f = xs[(n0 + g) * SP + k0 + t];
                float b1f = xs[(n0 + g) * SP + k0 + t + 4];
                uint32_t bh0 = f2tf32(b0f);
                uint32_t bh1 = f2tf32(b1f);
                uint32_t bl0 = __float_as_uint(b0f - __uint_as_float(bh0));
                uint32_t bl1 = __float_as_uint(b1f - __uint_as_float(bh1));
                mma_tf32(c[j], ah, bh0, bh1);
                mma_tf32(c[j], al, bh0, bh1);
                mma_tf32(c[j], ah, bl0, bl1);
            }
        }
        __syncthreads();
    }

    // --- transpose result through smem -> coalesced float4 global stores ---
    float* smo = sm;  // [128][OSP], 34.8KB, reuses xs area
    #pragma unroll
    for (int j = 0; j < 8; j++) {
        const int nloc = nb + j * 8 + 2 * t;
        smo[(nloc)     * OSP + m0 + g]     = c[j][0];
        smo[(nloc + 1) * OSP + m0 + g]     = c[j][1];
        smo[(nloc)     * OSP + m0 + g + 8] = c[j][2];
        smo[(nloc + 1) * OSP + m0 + g + 8] = c[j][3];
    }
    __syncthreads();

    for (int i = 0; i < 8; i++) {
        int idx4 = tid + 256 * i;          // 2048 float4 = 128 rows x 16
        int r    = idx4 >> 4;
        int c4   = idx4 & 15;
        int gn   = node0 + r;
        if (gn < N_NODES) {
            float rs = rsqrtf(g_deg[gn]);
            float4 v = *(float4*)&smo[r * OSP + c4 * 4];
            v.x *= rs; v.y *= rs; v.z *= rs; v.w *= rs;
            ((float4*)g_hs)[(size_t)gn * 16 + c4]  = v;
            ((float4*)g_acc)[(size_t)gn * 16 + c4] = v;   // self-loop term
        }
    }
}

// ---------------------------------------------------------------------------
// 4) edge scatter: acc[dst] += hs[src] * ew   (R4 winner — unchanged)
//    16 threads/edge, coalesced; 1 ld.v4 + 1 red.global.add.v4.f32 per lane.
// ---------------------------------------------------------------------------
__device__ __forceinline__ void red_v4(float* addr, float a, float b, float c, float d) {
    asm volatile("red.global.add.v4.f32 [%0], {%1, %2, %3, %4};"
                 :: "l"(addr), "f"(a), "f"(b), "f"(c), "f"(d) : "memory");
}

__global__ void __launch_bounds__(256) k_scatter(const int* __restrict__ ei,
                                                 const float* __restrict__ ew) {
    int t = blockIdx.x * blockDim.x + threadIdx.x;
    int e = t >> 4;
    if (e >= E_EDGES) return;
    int part = t & 15;

    const int   src = ei[e];
    const int   dst = ei[E_EDGES + e];
    const float w   = ew[e];

    float4 m = *(const float4*)&g_hs[src * OUT_DIM + (part << 2)];
    red_v4(&g_acc[dst * OUT_DIM + (part << 2)], m.x * w, m.y * w, m.z * w, m.w * w);
}

// ---------------------------------------------------------------------------
// 5) finalize: y = acc*dinv + b -> leaky_relu -> LayerNorm -> out
// ---------------------------------------------------------------------------
__global__ void k_finalize(const float* __restrict__ b, const float* __restrict__ gamma,
                           const float* __restrict__ beta, float* __restrict__ out) {
    int gw   = (blockIdx.x * blockDim.x + threadIdx.x) >> 5;
    int lane = threadIdx.x & 31;
    if (gw >= N_NODES) return;

    float dinv = rsqrtf(g_deg[gw]);
    int c0 = lane << 1;

    float2 a = *(const float2*)&g_acc[gw * OUT_DIM + c0];
    float y0 = a.x * dinv + b[c0];
    float y1 = a.y * dinv + b[c0 + 1];
    y0 = (y0 >= 0.f) ? y0 : NEG_SLOPE * y0;
    y1 = (y1 >= 0.f) ? y1 : NEG_SLOPE * y1;

    float s  = y0 + y1;
    float sq = y0 * y0 + y1 * y1;
    #pragma unroll
    for (int off = 16; off > 0; off >>= 1) {
        s  += __shfl_xor_sync(0xFFFFFFFFu, s,  off);
        sq += __shfl_xor_sync(0xFFFFFFFFu, sq, off);
    }
    float mu  = s * (1.f / 64.f);
    float var = sq * (1.f / 64.f) - mu * mu;
    float inv = rsqrtf(var + LN_EPS);

    float o0 = (y0 - mu) * inv * gamma[c0]     + beta[c0];
    float o1 = (y1 - mu) * inv * gamma[c0 + 1] + beta[c0 + 1];
    float2 r; r.x = o0; r.y = o1;
    *(float2*)&out[gw * OUT_DIM + c0] = r;
}

// ---------------------------------------------------------------------------
extern "C" void kernel_launch(void* const* d_in, const int* in_sizes, int n_in,
                              void* d_out, int out_size) {
    const float* x     = (const float*)d_in[0];
    const int*   ei    = (const int*)  d_in[1];
    const float* ew    = (const float*)d_in[2];
    const float* W     = (const float*)d_in[3];
    const float* b     = (const float*)d_in[4];
    const float* gamma = (const float*)d_in[5];
    const float* beta  = (const float*)d_in[6];
    float* out = (float*)d_out;

    const int gemm_smem = (GEMM_ROWS * SP + OUT_DIM * SP) * (int)sizeof(float); // ~101KB
    cudaFuncSetAttribute(k_gemm, cudaFuncAttributeMaxDynamicSharedMemorySize, gemm_smem);

    k_init_deg   <<<(N_NODES + 255) / 256, 256>>>();
    k_deg_scatter<<<(E_EDGES + 255) / 256, 256>>>(ei, ew);
    k_gemm       <<<(N_NODES + GEMM_ROWS - 1) / GEMM_ROWS, 256, gemm_smem>>>(x, W);
    k_scatter    <<<((long long)E_EDGES * 16 + 255) / 256, 256>>>(ei, ew);
    k_finalize   <<<(N_NODES * 32 + 255) / 256, 256>>>(b, gamma, beta, out);
}